// round 7
// baseline (speedup 1.0000x reference)
#include <cuda_runtime.h>

#define H 512
#define W 512
#define NB 32

#define SQRT_APPROX(d, a) \
    asm("sqrt.approx.f32 %0, %1;" : "=f"(d) : "f"(a))

// R6 per-thread code, new block mapping for vertical L1 reuse:
// block = 8 warps = 8 vertically-adjacent rows of one 128-px strip.
// Each input row is read by up to 3 warps of the SAME block -> L1 hits,
// cutting L2 read traffic ~3x.
// grid = (strip=4, rowblock=64, n=32)
__global__ __launch_bounds__(256) void sqdiff_mag_kernel(
    const float* __restrict__ x, float* __restrict__ out)
{
    int lane  = threadIdx.x & 31;
    int warp  = threadIdx.x >> 5;            // 0..7 = row within block
    int strip = blockIdx.x;                  // 0..3
    int h     = (blockIdx.y << 3) + warp;    // row
    int n     = blockIdx.z;                  // batch

    int wbase = strip << 7;                  // 0,128,256,384
    int w     = wbase + (lane << 2);

    const size_t plane = (size_t)H * W;
    const float* g = x + ((size_t)n * 3 + 1) * plane;   // channel 1

    float rm[6], rc[6], rp[6];

    #define LOAD_ROW(dst, hh)                                                  \
    {                                                                          \
        const float* p = g + (size_t)(hh) * W + w;                             \
        float4 v = *reinterpret_cast<const float4*>(p);                        \
        dst[1] = v.x; dst[2] = v.y; dst[3] = v.z; dst[4] = v.w;                \
        float lft = __shfl_up_sync(0xffffffffu, v.w, 1);                       \
        float rgt = __shfl_down_sync(0xffffffffu, v.x, 1);                     \
        if (lane == 0)  lft = (wbase > 0)       ? __ldg(p - 1) : 0.0f;         \
        if (lane == 31) rgt = (wbase + 128 < W) ? __ldg(p + 4) : 0.0f;         \
        dst[0] = lft; dst[5] = rgt;                                            \
    }

    LOAD_ROW(rc, h)
    if (h > 0) {
        LOAD_ROW(rm, h - 1)
    } else {
        #pragma unroll
        for (int i = 0; i < 6; i++) rm[i] = 0.0f;
    }
    if (h + 1 < H) {
        LOAD_ROW(rp, h + 1)
    } else {
        #pragma unroll
        for (int i = 0; i < 6; i++) rp[i] = 0.0f;
    }
    #undef LOAD_ROW

    float4 res;
    float* resp = reinterpret_cast<float*>(&res);

    #pragma unroll
    for (int i = 0; i < 4; i++) {
        float c  = rc[i + 1];
        float d0 = c - rc[i + 2];
        float d1 = c - rc[i];
        float d2 = c - rp[i + 1];
        float d3 = c - rm[i + 1];
        float d4 = c - rp[i + 2];
        float d5 = c - rp[i];
        float d6 = c - rm[i + 2];
        float d7 = c - rm[i];
        float s = d0 * d0;
        s = fmaf(d1, d1, s);
        s = fmaf(d2, d2, s);
        s = fmaf(d3, d3, s);
        s = fmaf(d4, d4, s);
        s = fmaf(d5, d5, s);
        s = fmaf(d6, d6, s);
        s = fmaf(d7, d7, s);
        SQRT_APPROX(resp[i], s);
    }

    float* ob = out + (size_t)n * 3 * plane + (size_t)h * W + w;
    __stcs(reinterpret_cast<float4*>(ob),             res);
    __stcs(reinterpret_cast<float4*>(ob + plane),     res);
    __stcs(reinterpret_cast<float4*>(ob + 2 * plane), res);
}

extern "C" void kernel_launch(void* const* d_in, const int* in_sizes, int n_in,
                              void* d_out, int out_size)
{
    const float* x = (const float*)d_in[0];
    float* out = (float*)d_out;

    dim3 grid(4, H / 8, NB);   // 4 strips x 64 row-blocks x 32 batches = 8192
    sqdiff_mag_kernel<<<grid, 256>>>(x, out);
}

// round 8
// speedup vs baseline: 1.0958x; 1.0958x over previous
#include <cuda_runtime.h>

#define H 512
#define W 512
#define NB 32

#define SQRT_APPROX(d, a) \
    asm("sqrt.approx.f32 %0, %1;" : "=f"(d) : "f"(a))

// R6 per-thread code. Block = 1024 threads = 8 FULL rows (32 warps, 4 per row).
// Vertical neighbors are warps in the same CTA -> input rows are L1-reused
// (10 distinct rows loaded per 8 output rows vs 12 in R6), while stores stay
// contiguous full-row bursts (R7's fragmentation mistake avoided).
// Default .wb stores: output stays L2-resident across graph replays.
__global__ __launch_bounds__(1024) void sqdiff_mag_kernel(
    const float* __restrict__ x, float* __restrict__ out)
{
    int lane   = threadIdx.x & 31;
    int warp   = threadIdx.x >> 5;         // 0..31
    int rowblk = warp >> 2;                // 0..7 row within block
    int strip  = warp & 3;                 // 0..3 column strip

    int h = (blockIdx.x << 3) + rowblk;
    int n = blockIdx.y;

    int wbase = strip << 7;                // 0,128,256,384
    int w     = wbase + (lane << 2);

    const size_t plane = (size_t)H * W;
    const float* g = x + ((size_t)n * 3 + 1) * plane;   // channel 1

    float rm[6], rc[6], rp[6];

    #define LOAD_ROW(dst, hh)                                                  \
    {                                                                          \
        const float* p = g + (size_t)(hh) * W + w;                             \
        float4 v = *reinterpret_cast<const float4*>(p);                        \
        dst[1] = v.x; dst[2] = v.y; dst[3] = v.z; dst[4] = v.w;                \
        float lft = __shfl_up_sync(0xffffffffu, v.w, 1);                       \
        float rgt = __shfl_down_sync(0xffffffffu, v.x, 1);                     \
        if (lane == 0)  lft = (wbase > 0)       ? __ldg(p - 1) : 0.0f;         \
        if (lane == 31) rgt = (wbase + 128 < W) ? __ldg(p + 4) : 0.0f;         \
        dst[0] = lft; dst[5] = rgt;                                            \
    }

    LOAD_ROW(rc, h)
    if (h > 0) {
        LOAD_ROW(rm, h - 1)
    } else {
        #pragma unroll
        for (int i = 0; i < 6; i++) rm[i] = 0.0f;
    }
    if (h + 1 < H) {
        LOAD_ROW(rp, h + 1)
    } else {
        #pragma unroll
        for (int i = 0; i < 6; i++) rp[i] = 0.0f;
    }
    #undef LOAD_ROW

    float4 res;
    float* resp = reinterpret_cast<float*>(&res);

    #pragma unroll
    for (int i = 0; i < 4; i++) {
        float c  = rc[i + 1];
        float d0 = c - rc[i + 2];
        float d1 = c - rc[i];
        float d2 = c - rp[i + 1];
        float d3 = c - rm[i + 1];
        float d4 = c - rp[i + 2];
        float d5 = c - rp[i];
        float d6 = c - rm[i + 2];
        float d7 = c - rm[i];
        float s = d0 * d0;
        s = fmaf(d1, d1, s);
        s = fmaf(d2, d2, s);
        s = fmaf(d3, d3, s);
        s = fmaf(d4, d4, s);
        s = fmaf(d5, d5, s);
        s = fmaf(d6, d6, s);
        s = fmaf(d7, d7, s);
        SQRT_APPROX(resp[i], s);
    }

    float* ob = out + (size_t)n * 3 * plane + (size_t)h * W + w;
    *reinterpret_cast<float4*>(ob)             = res;
    *reinterpret_cast<float4*>(ob + plane)     = res;
    *reinterpret_cast<float4*>(ob + 2 * plane) = res;
}

extern "C" void kernel_launch(void* const* d_in, const int* in_sizes, int n_in,
                              void* d_out, int out_size)
{
    const float* x = (const float*)d_in[0];
    float* out = (float*)d_out;

    dim3 grid(H / 8, NB);   // 64 x 32 = 2048 CTAs of 1024 threads
    sqdiff_mag_kernel<<<grid, 1024>>>(x, out);
}

// round 9
// speedup vs baseline: 1.2930x; 1.1800x over previous
#include <cuda_runtime.h>

#define H 512
#define W 512
#define NB 32

#define SQRT_APPROX(d, a) \
    asm("sqrt.approx.f32 %0, %1;" : "=f"(d) : "f"(a))

// R6 per-thread code, 512-thread full-width CTA = 4 adjacent rows.
// - stores remain contiguous full-row bursts (16 warps: 4 per row)
// - vertical input reuse within the CTA via L1 (6 rows loaded / 4 produced)
// grid = (H/4, NB) = (128, 32) = 4096 CTAs
__global__ __launch_bounds__(512) void sqdiff_mag_kernel(
    const float* __restrict__ x, float* __restrict__ out)
{
    int lane   = threadIdx.x & 31;
    int warp   = threadIdx.x >> 5;         // 0..15
    int rowblk = warp >> 2;                // 0..3 row within CTA
    int strip  = warp & 3;                 // 0..3 column strip

    int h = (blockIdx.x << 2) + rowblk;
    int n = blockIdx.y;

    int wbase = strip << 7;                // 0,128,256,384
    int w     = wbase + (lane << 2);

    const size_t plane = (size_t)H * W;
    const float* g = x + ((size_t)n * 3 + 1) * plane;   // channel 1

    float rm[6], rc[6], rp[6];

    #define LOAD_ROW(dst, hh)                                                  \
    {                                                                          \
        const float* p = g + (size_t)(hh) * W + w;                             \
        float4 v = *reinterpret_cast<const float4*>(p);                        \
        dst[1] = v.x; dst[2] = v.y; dst[3] = v.z; dst[4] = v.w;                \
        float lft = __shfl_up_sync(0xffffffffu, v.w, 1);                       \
        float rgt = __shfl_down_sync(0xffffffffu, v.x, 1);                     \
        if (lane == 0)  lft = (wbase > 0)       ? __ldg(p - 1) : 0.0f;         \
        if (lane == 31) rgt = (wbase + 128 < W) ? __ldg(p + 4) : 0.0f;         \
        dst[0] = lft; dst[5] = rgt;                                            \
    }

    LOAD_ROW(rc, h)
    if (h > 0) {
        LOAD_ROW(rm, h - 1)
    } else {
        #pragma unroll
        for (int i = 0; i < 6; i++) rm[i] = 0.0f;
    }
    if (h + 1 < H) {
        LOAD_ROW(rp, h + 1)
    } else {
        #pragma unroll
        for (int i = 0; i < 6; i++) rp[i] = 0.0f;
    }
    #undef LOAD_ROW

    float4 res;
    float* resp = reinterpret_cast<float*>(&res);

    #pragma unroll
    for (int i = 0; i < 4; i++) {
        float c  = rc[i + 1];
        float d0 = c - rc[i + 2];
        float d1 = c - rc[i];
        float d2 = c - rp[i + 1];
        float d3 = c - rm[i + 1];
        float d4 = c - rp[i + 2];
        float d5 = c - rp[i];
        float d6 = c - rm[i + 2];
        float d7 = c - rm[i];
        float s = d0 * d0;
        s = fmaf(d1, d1, s);
        s = fmaf(d2, d2, s);
        s = fmaf(d3, d3, s);
        s = fmaf(d4, d4, s);
        s = fmaf(d5, d5, s);
        s = fmaf(d6, d6, s);
        s = fmaf(d7, d7, s);
        SQRT_APPROX(resp[i], s);
    }

    float* ob = out + (size_t)n * 3 * plane + (size_t)h * W + w;
    __stcs(reinterpret_cast<float4*>(ob),             res);
    __stcs(reinterpret_cast<float4*>(ob + plane),     res);
    __stcs(reinterpret_cast<float4*>(ob + 2 * plane), res);
}

extern "C" void kernel_launch(void* const* d_in, const int* in_sizes, int n_in,
                              void* d_out, int out_size)
{
    const float* x = (const float*)d_in[0];
    float* out = (float*)d_out;

    dim3 grid(H / 4, NB);   // 128 x 32 = 4096 CTAs of 512 threads
    sqdiff_mag_kernel<<<grid, 512>>>(x, out);
}